// round 16
// baseline (speedup 1.0000x reference)
#include <cuda_runtime.h>
#include <cuda_bf16.h>
#include <cstdint>

// GCN on complete graph + self-loops == per-batch mean pooling -> per-batch
// 4-layer MLP on the mean node feature.
// Two kernels: prep converts W2/Wm1 to transposed, k-padded bf16 hi/lo
// arrays; mlp TMA-stages them (split barriers: W2 then Wm1) and runs L2/L3
// as warp-level mma.sync.m16n8k16 with hi/lo split using THREE independent
// accumulators (8-deep chains instead of 24). L1 (K=14) is scalar f32.
// grid=64 CTAs x 16 batch rows, NT=512.

#define NT 512
#define MR 16
#define KPAD 136    // u16 k-stride (u32 stride 68) -> conflict-free frag LDS

__device__ unsigned short g_w2hi[128 * KPAD], g_w2lo[128 * KPAD];
__device__ unsigned short g_m1hi[128 * KPAD], g_m1lo[128 * KPAD];

// ---- dynamic smem byte offsets ----
#define OW2H 0
#define WB   (128 * KPAD * 2)      // 34816
#define OW2L (OW2H + WB)
#define OM1H (OW2L + WB)
#define OM1L (OM1H + WB)
#define OA1H (OM1L + WB)           // act tiles 16 x KPAD u16
#define AB   (MR * KPAD * 2)       // 4352
#define OA1L (OA1H + AB)
#define OA2H (OA1L + AB)
#define OA2L (OA2H + AB)
#define OSM  (OA2L + AB)           // f32 [16][132]
#define OFB  (OSM + 16 * 132 * 4)  // f32 [16][16]
#define OPART (OFB + 1024)         // float2 [448]
#define OB2V (OPART + 3584)
#define OBM1 (OB2V + 512)
#define OWM2 (OBM1 + 512)          // f32 [512]
#define OBM2 (OWM2 + 2048)         // f32 [4]
#define OSP  (OBM2 + 16)           // f32 [512]
#define OSO  (OSP + 2048)          // f32 [64]
#define OMB  (OSO + 256)           // 2 mbarriers
#define SMEM_BYTES (OMB + 16)

__device__ __forceinline__ uint32_t s2u(const void* p) {
    return (uint32_t)__cvta_generic_to_shared(p);
}
#define MBARRIER_INIT(mb, c) \
    asm volatile("mbarrier.init.shared.b64 [%0], %1;" :: "r"(mb), "r"(c) : "memory")
__device__ __forceinline__ void mbar_expect(uint32_t a, uint32_t bytes) {
    asm volatile("mbarrier.arrive.expect_tx.shared.b64 _, [%0], %1;"
                 :: "r"(a), "r"(bytes) : "memory");
}
__device__ __forceinline__ void bulk_g2s(uint32_t dst, const void* src,
                                         uint32_t bytes, uint32_t mbar) {
    asm volatile("cp.async.bulk.shared::cluster.global.mbarrier::complete_tx::bytes "
                 "[%0], [%1], %2, [%3];"
                 :: "r"(dst), "l"(src), "r"(bytes), "r"(mbar) : "memory");
}
__device__ __forceinline__ void mbar_wait(uint32_t a, uint32_t parity) {
    asm volatile(
        "{\n\t.reg .pred P;\n"
        "WAIT_%=:\n\t"
        "mbarrier.try_wait.parity.shared.b64 P, [%0], %1, 0x989680;\n\t"
        "@P bra.uni DONE_%=;\n\t"
        "bra.uni WAIT_%=;\n"
        "DONE_%=:\n\t}"
        :: "r"(a), "r"(parity) : "memory");
}

__device__ __forceinline__ uint32_t packbf(float lo, float hi) {
    uint32_t r;
    asm("cvt.rn.bf16x2.f32 %0, %1, %2;" : "=r"(r) : "f"(hi), "f"(lo));
    return r;
}
__device__ __forceinline__ void split2u(float x0, float x1, uint32_t& hp, uint32_t& lp) {
    hp = packbf(x0, x1);
    const float h0 = __uint_as_float(hp << 16);
    const float h1 = __uint_as_float(hp & 0xFFFF0000u);
    lp = packbf(x0 - h0, x1 - h1);
}
__device__ __forceinline__ void split2f(float x, unsigned short& h, unsigned short& l) {
    __nv_bfloat16 hb = __float2bfloat16_rn(x);
    float r = x - __bfloat162float(hb);
    h = __bfloat16_as_ushort(hb);
    l = __bfloat16_as_ushort(__float2bfloat16_rn(r));
}

// prep: grid = 128 (k), block = 128 (n). Coalesced LDG; scattered u16 STG
// (small total: 2 x 64KB). Measured ~1.5us incl. launch in R12/R13.
__global__ void prep_kernel(const float* __restrict__ W2,
                            const float* __restrict__ Wm1) {
    const int k = blockIdx.x, n = threadIdx.x;
    unsigned short h, l;
    split2f(W2[k * 128 + n], h, l);
    g_w2hi[n * KPAD + k] = h;  g_w2lo[n * KPAD + k] = l;
    split2f(Wm1[k * 128 + n], h, l);
    g_m1hi[n * KPAD + k] = h;  g_m1lo[n * KPAD + k] = l;
}

__device__ __forceinline__ void mma16816(float c[4],
                                         uint32_t a0, uint32_t a1, uint32_t a2, uint32_t a3,
                                         uint32_t b0, uint32_t b1) {
    asm volatile(
        "mma.sync.aligned.m16n8k16.row.col.f32.bf16.bf16.f32 "
        "{%0,%1,%2,%3}, {%4,%5,%6,%7}, {%8,%9}, {%0,%1,%2,%3};"
        : "+f"(c[0]), "+f"(c[1]), "+f"(c[2]), "+f"(c[3])
        : "r"(a0), "r"(a1), "r"(a2), "r"(a3), "r"(b0), "r"(b1));
}

// One 128-k layer. THREE independent accumulators (hi*hi / hi*lo / lo*hi),
// each an 8-deep MMA chain, summed in the epilogue.
template<bool F32OUT>
__device__ __forceinline__ void layer128(
    const unsigned short* __restrict__ sInHi, const unsigned short* __restrict__ sInLo,
    const unsigned short* __restrict__ sWhi,  const unsigned short* __restrict__ sWlo,
    const float* __restrict__ bias,
    unsigned short* __restrict__ sOutHi, unsigned short* __restrict__ sOutLo,
    float* __restrict__ sMout, int wid, int lane)
{
    const int g = lane >> 2, t = lane & 3;
    const int n0 = wid * 8 + g;
    float ca[4] = {0.f, 0.f, 0.f, 0.f};
    float cb[4] = {0.f, 0.f, 0.f, 0.f};
    float cc[4] = {0.f, 0.f, 0.f, 0.f};

    #pragma unroll
    for (int s = 0; s < 8; s++) {
        const int ko = 16 * s + 2 * t;
        const uint32_t ah0 = *(const uint32_t*)(sInHi + g * KPAD + ko);
        const uint32_t ah1 = *(const uint32_t*)(sInHi + (g + 8) * KPAD + ko);
        const uint32_t ah2 = *(const uint32_t*)(sInHi + g * KPAD + ko + 8);
        const uint32_t ah3 = *(const uint32_t*)(sInHi + (g + 8) * KPAD + ko + 8);
        const uint32_t al0 = *(const uint32_t*)(sInLo + g * KPAD + ko);
        const uint32_t al1 = *(const uint32_t*)(sInLo + (g + 8) * KPAD + ko);
        const uint32_t al2 = *(const uint32_t*)(sInLo + g * KPAD + ko + 8);
        const uint32_t al3 = *(const uint32_t*)(sInLo + (g + 8) * KPAD + ko + 8);

        const uint32_t bh0 = *(const uint32_t*)(sWhi + n0 * KPAD + ko);
        const uint32_t bh1 = *(const uint32_t*)(sWhi + n0 * KPAD + ko + 8);
        const uint32_t bl0 = *(const uint32_t*)(sWlo + n0 * KPAD + ko);
        const uint32_t bl1 = *(const uint32_t*)(sWlo + n0 * KPAD + ko + 8);

        mma16816(ca, ah0, ah1, ah2, ah3, bh0, bh1);   // hi*hi
        mma16816(cb, ah0, ah1, ah2, ah3, bl0, bl1);   // hi*lo
        mma16816(cc, al0, al1, al2, al3, bh0, bh1);   // lo*hi
    }

    const int col = wid * 8 + 2 * t;
    const float bx = bias[col], by = bias[col + 1];
    const float x0 = fmaxf(ca[0] + cb[0] + cc[0] + bx, 0.f);
    const float x1 = fmaxf(ca[1] + cb[1] + cc[1] + by, 0.f);
    const float x2 = fmaxf(ca[2] + cb[2] + cc[2] + bx, 0.f);
    const float x3 = fmaxf(ca[3] + cb[3] + cc[3] + by, 0.f);
    if (F32OUT) {
        *(float2*)(sMout + g * 132 + col)       = make_float2(x0, x1);
        *(float2*)(sMout + (g + 8) * 132 + col) = make_float2(x2, x3);
    } else {
        uint32_t hp, lp;
        split2u(x0, x1, hp, lp);
        *(uint32_t*)(sOutHi + g * KPAD + col) = hp;
        *(uint32_t*)(sOutLo + g * KPAD + col) = lp;
        split2u(x2, x3, hp, lp);
        *(uint32_t*)(sOutHi + (g + 8) * KPAD + col) = hp;
        *(uint32_t*)(sOutLo + (g + 8) * KPAD + col) = lp;
    }
}

__global__ __launch_bounds__(NT, 1) void mlp_kernel(
    const float* __restrict__ obs,
    const float* __restrict__ W1,  const float* __restrict__ b1,
    const float* __restrict__ b2,  const float* __restrict__ bm1,
    const float* __restrict__ Wm2, const float* __restrict__ bm2,
    float* __restrict__ out, int std_off)
{
    extern __shared__ __align__(16) char smem[];
    unsigned short* sW2h = (unsigned short*)(smem + OW2H);
    unsigned short* sW2l = (unsigned short*)(smem + OW2L);
    unsigned short* sM1h = (unsigned short*)(smem + OM1H);
    unsigned short* sM1l = (unsigned short*)(smem + OM1L);
    unsigned short* sA1h = (unsigned short*)(smem + OA1H);
    unsigned short* sA1l = (unsigned short*)(smem + OA1L);
    unsigned short* sA2h = (unsigned short*)(smem + OA2H);
    unsigned short* sA2l = (unsigned short*)(smem + OA2L);
    float*  sM    = (float*)(smem + OSM);
    float*  sFB   = (float*)(smem + OFB);
    float2* sPart = (float2*)(smem + OPART);
    float*  sB2   = (float*)(smem + OB2V);
    float*  sBm1  = (float*)(smem + OBM1);
    float*  sWm2v = (float*)(smem + OWM2);
    float*  sBm2  = (float*)(smem + OBM2);
    float*  sP    = (float*)(smem + OSP);
    float*  sO    = (float*)(smem + OSO);

    const int tid = threadIdx.x, wid = tid >> 5, lane = tid & 31;
    const int base = blockIdx.x * MR;
    const uint32_t mbar0 = s2u(smem + OMB);
    const uint32_t mbar1 = mbar0 + 8;

    if (tid == 0) { MBARRIER_INIT(mbar0, 1); MBARRIER_INIT(mbar1, 1); }
    __syncthreads();
    if (tid == 0) {
        mbar_expect(mbar0, 2 * WB);
        bulk_g2s(s2u(smem + OW2H), g_w2hi, WB, mbar0);
        bulk_g2s(s2u(smem + OW2L), g_w2lo, WB, mbar0);
        mbar_expect(mbar1, 2 * WB);
        bulk_g2s(s2u(smem + OM1H), g_m1hi, WB, mbar1);
        bulk_g2s(s2u(smem + OM1L), g_m1lo, WB, mbar1);
    }

    // ---- small params ----
    sWm2v[tid] = Wm2[tid];
    if (tid < 128) { sB2[tid] = b2[tid]; sBm1[tid] = bm1[tid]; }
    if (tid < 4) sBm2[tid] = bm2[tid];

    // ---- fbar partials: 448 threads = 16r x 7 dim-pairs x 4 node-quarters ----
    if (tid < 448) {
        const int r = tid & 15, pq = tid >> 4;
        const int p = pq % 7, q = pq / 7;
        const float* s = obs + (size_t)(base + r) * 512 + 2 + 2 * p + q * 128;
        float s0 = 0.f, s1 = 0.f;
        #pragma unroll
        for (int n = 0; n < 8; n++) {
            const float2 v = *(const float2*)(s + n * 16);
            s0 += v.x; s1 += v.y;
        }
        sPart[r * 28 + pq] = make_float2(s0, s1);
    }
    __syncthreads();

    // ---- fbar reduce: 112 threads (r, p) ----
    if (tid < 112) {
        const int r = tid & 15, p = tid >> 4;
        float s0 = 0.f, s1 = 0.f;
        #pragma unroll
        for (int q = 0; q < 4; q++) {
            const float2 v = sPart[r * 28 + q * 7 + p];
            s0 += v.x; s1 += v.y;
        }
        sFB[r * 16 + 2 * p]     = s0 * 0.03125f;
        sFB[r * 16 + 2 * p + 1] = s1 * 0.03125f;
    }
    __syncthreads();

    // ---- L1 scalar f32: h1 = relu(fbar @ W1 + b1) -> A2 bf16 hi/lo ----
    {
        const int r = tid >> 5, j = tid & 31, c0 = 4 * j;
        float4 acc = *(const float4*)(b1 + c0);
        #pragma unroll
        for (int d = 0; d < 14; d++) {
            const float f = sFB[r * 16 + d];
            const float4 w = *(const float4*)(W1 + d * 128 + c0);
            acc.x = fmaf(f, w.x, acc.x);
            acc.y = fmaf(f, w.y, acc.y);
            acc.z = fmaf(f, w.z, acc.z);
            acc.w = fmaf(f, w.w, acc.w);
        }
        acc.x = fmaxf(acc.x, 0.f); acc.y = fmaxf(acc.y, 0.f);
        acc.z = fmaxf(acc.z, 0.f); acc.w = fmaxf(acc.w, 0.f);
        uint32_t hp, lp;
        split2u(acc.x, acc.y, hp, lp);
        ((uint32_t*)sA2h)[r * (KPAD / 2) + 2 * j]     = hp;
        ((uint32_t*)sA2l)[r * (KPAD / 2) + 2 * j]     = lp;
        split2u(acc.z, acc.w, hp, lp);
        ((uint32_t*)sA2h)[r * (KPAD / 2) + 2 * j + 1] = hp;
        ((uint32_t*)sA2l)[r * (KPAD / 2) + 2 * j + 1] = lp;
    }

    // ---- W2 staged? ----
    mbar_wait(mbar0, 0);
    __syncthreads();

    // ---- L2: h2 = relu(h1 @ W2 + b2) : A2 -> A1 ----
    layer128<false>(sA2h, sA2l, sW2h, sW2l, sB2, sA1h, sA1l, nullptr, wid, lane);

    // ---- Wm1 staged? (delivery covered by L2 compute) ----
    mbar_wait(mbar1, 0);
    __syncthreads();

    // ---- L3: m = relu(h2 @ Wm1 + bm1) : A1 -> sM f32 ----
    layer128<true>(sA1h, sA1l, sM1h, sM1l, sBm1, nullptr, nullptr, sM, wid, lane);
    __syncthreads();

    // ---- tail: o = m @ Wm2 + bm2 : 512 = 16r x 4c x 8 k-slices ----
    {
        const int r = tid >> 5, cc = (tid >> 3) & 3, s = tid & 7;
        float p = 0.f;
        #pragma unroll
        for (int i = 0; i < 16; i++) {
            const int k = s * 16 + i;
            p = fmaf(sM[r * 132 + k], sWm2v[k * 4 + cc], p);
        }
        sP[tid] = p;
    }
    __syncthreads();
    if (tid < 64) {
        const int r = tid >> 2, cc = tid & 3;
        float o = sBm2[cc];
        #pragma unroll
        for (int s = 0; s < 8; s++) o += sP[r * 32 + cc * 8 + s];
        if (cc >= 2) o = __expf(-5.0f + 3.5f * (tanhf(o) + 1.0f));
        sO[r * 4 + cc] = o;    // [mu0, mu1, std0, std1]
    }
    __syncthreads();

    // ---- write: 512 float4 stores, one per thread, coalesced ----
    {
        const int plane = tid >> 8;
        const int r = (tid >> 4) & 15;
        const int q = tid & 15;
        const float v0 = sO[r * 4 + 2 * plane];
        const float v1 = sO[r * 4 + 2 * plane + 1];
        float* dst = out + (plane ? (size_t)std_off : 0) + (size_t)(base + r) * 64;
        ((float4*)dst)[q] = make_float4(v0, v1, v0, v1);
    }
}

extern "C" void kernel_launch(void* const* d_in, const int* in_sizes, int n_in,
                              void* d_out, int out_size) {
    const float* obs = (const float*)d_in[0];
    const float* W1  = (const float*)d_in[1];
    const float* b1  = (const float*)d_in[2];
    const float* W2  = (const float*)d_in[3];
    const float* b2  = (const float*)d_in[4];
    const float* Wm1 = (const float*)d_in[5];
    const float* bm1 = (const float*)d_in[6];
    const float* Wm2 = (const float*)d_in[7];
    const float* bm2 = (const float*)d_in[8];
    float* out = (float*)d_out;

    const int bs = in_sizes[0] / 512;     // 1024
    const int std_off = bs * 64;
    const int grid = bs / MR;             // 64

    prep_kernel<<<128, 128>>>(W2, Wm1);
    cudaFuncSetAttribute(mlp_kernel,
                         cudaFuncAttributeMaxDynamicSharedMemorySize, SMEM_BYTES);
    mlp_kernel<<<grid, NT, SMEM_BYTES>>>(obs, W1, b1, b2, bm1, Wm2, bm2,
                                         out, std_off);
}

// round 17
// speedup vs baseline: 1.1830x; 1.1830x over previous
#include <cuda_runtime.h>
#include <cuda_bf16.h>
#include <cstdint>

// GCN on complete graph + self-loops == per-batch mean pooling -> per-batch
// 4-layer MLP on the mean node feature.
// Single-kernel tensor-core version (mma.sync.m16n8k16 bf16, f32 accum,
// hi/lo split = 3 MMAs/step, single accumulator chain as in the fastest
// measured variant). Weights converted in-kernel to a PAIR-PACKED layout
// {W[2p][n],W[2p+1][n]} @ [p*136+n] u32 — coalesced LDG (volatile-batched),
// coalesced conflict-free STS, and the u32 IS the MMA b-fragment word.
// grid = 64 CTAs x 16 batch rows, NT = 512.

#define NT 512
#define MR 16
#define KPAD 136      // act u16 k-stride; weight pair-row u32 stride is also 136

// ---- dynamic smem byte offsets ----
#define OW2H 0
#define WB   (64 * 136 * 4)        // 34816 (64 pair-rows x 136 u32)
#define OW2L (OW2H + WB)
#define OM1H (OW2L + WB)
#define OM1L (OM1H + WB)
#define OA1H (OM1L + WB)           // act tiles 16 x KPAD u16
#define AB   (MR * KPAD * 2)       // 4352
#define OA1L (OA1H + AB)
#define OA2H (OA1L + AB)
#define OA2L (OA2H + AB)
#define OSM  (OA2L + AB)           // f32 [16][132]
#define OFB  (OSM + 16 * 132 * 4)  // f32 [16][16]
#define OPART (OFB + 1024)         // float2 [448]
#define OB2V (OPART + 3584)
#define OBM1 (OB2V + 512)
#define OWM2 (OBM1 + 512)          // f32 [512]
#define OBM2 (OWM2 + 2048)         // f32 [4]
#define OSP  (OBM2 + 16)           // f32 [512]
#define OSO  (OSP + 2048)          // f32 [64]
#define SMEM_BYTES (OSO + 256)

__device__ __forceinline__ uint32_t packbf(float lo, float hi) {
    uint32_t r;
    asm("cvt.rn.bf16x2.f32 %0, %1, %2;" : "=r"(r) : "f"(hi), "f"(lo));
    return r;
}
// hp = {bf16(x0) lo-half, bf16(x1) hi-half}; lp = residuals
__device__ __forceinline__ void split2u(float x0, float x1, uint32_t& hp, uint32_t& lp) {
    hp = packbf(x0, x1);
    const float h0 = __uint_as_float(hp << 16);
    const float h1 = __uint_as_float(hp & 0xFFFF0000u);
    lp = packbf(x0 - h0, x1 - h1);
}
// volatile global load: forces ptxas to keep the batch (cannot sink)
__device__ __forceinline__ float ldgv(const float* p) {
    float v;
    asm volatile("ld.global.nc.f32 %0, [%1];" : "=f"(v) : "l"(p));
    return v;
}

__device__ __forceinline__ void mma16816(float c[4],
                                         uint32_t a0, uint32_t a1, uint32_t a2, uint32_t a3,
                                         uint32_t b0, uint32_t b1) {
    asm volatile(
        "mma.sync.aligned.m16n8k16.row.col.f32.bf16.bf16.f32 "
        "{%0,%1,%2,%3}, {%4,%5,%6,%7}, {%8,%9}, {%0,%1,%2,%3};"
        : "+f"(c[0]), "+f"(c[1]), "+f"(c[2]), "+f"(c[3])
        : "r"(a0), "r"(a1), "r"(a2), "r"(a3), "r"(b0), "r"(b1));
}

// Convert W[k][n] (128x128 f32) -> pair-packed bf16 hi/lo u32 tiles:
// sH[p*136+n] = {hi(W[2p][n]), hi(W[2p+1][n])}, sL = residuals.
// Two batches of 8 units: 16 volatile LDGs in flight, then convert+STS.
__device__ __forceinline__ void convert_w_pp(const float* __restrict__ W,
                                             uint32_t* __restrict__ sH,
                                             uint32_t* __restrict__ sL, int tid) {
    #pragma unroll
    for (int half = 0; half < 2; half++) {
        float va[8], vb[8];
        #pragma unroll
        for (int j = 0; j < 8; j++) {
            const int u = tid + 512 * (half * 8 + j);
            const int p = u >> 7, n = u & 127;
            va[j] = ldgv(W + (2 * p) * 128 + n);
            vb[j] = ldgv(W + (2 * p + 1) * 128 + n);
        }
        #pragma unroll
        for (int j = 0; j < 8; j++) {
            const int u = tid + 512 * (half * 8 + j);
            const int p = u >> 7, n = u & 127;
            uint32_t hp, lp;
            split2u(va[j], vb[j], hp, lp);
            sH[p * 136 + n] = hp;
            sL[p * 136 + n] = lp;
        }
    }
}

// One 128-k layer. Acts: u16 hi/lo [16][KPAD]. Weights: pair-packed u32
// hi/lo [64][136]. Single accumulator (R13-verified fastest). 16 warps x
// one 8-col n-tile, M=16.
template<bool F32OUT>
__device__ __forceinline__ void layer128(
    const unsigned short* __restrict__ sInHi, const unsigned short* __restrict__ sInLo,
    const uint32_t* __restrict__ sWhi,        const uint32_t* __restrict__ sWlo,
    const float* __restrict__ bias,
    unsigned short* __restrict__ sOutHi, unsigned short* __restrict__ sOutLo,
    float* __restrict__ sMout, int wid, int lane)
{
    const int g = lane >> 2, t = lane & 3;
    const int n0 = wid * 8 + g;
    float c0[4] = {0.f, 0.f, 0.f, 0.f};

    #pragma unroll
    for (int s = 0; s < 8; s++) {
        const int ko = 16 * s + 2 * t;
        const uint32_t ah0 = *(const uint32_t*)(sInHi + g * KPAD + ko);
        const uint32_t ah1 = *(const uint32_t*)(sInHi + (g + 8) * KPAD + ko);
        const uint32_t ah2 = *(const uint32_t*)(sInHi + g * KPAD + ko + 8);
        const uint32_t ah3 = *(const uint32_t*)(sInHi + (g + 8) * KPAD + ko + 8);
        const uint32_t al0 = *(const uint32_t*)(sInLo + g * KPAD + ko);
        const uint32_t al1 = *(const uint32_t*)(sInLo + (g + 8) * KPAD + ko);
        const uint32_t al2 = *(const uint32_t*)(sInLo + g * KPAD + ko + 8);
        const uint32_t al3 = *(const uint32_t*)(sInLo + (g + 8) * KPAD + ko + 8);

        // pair index for k=ko is ko/2 = 8s+t; k=ko+8 -> 8s+t+4
        const uint32_t bh0 = sWhi[(8 * s + t) * 136 + n0];
        const uint32_t bh1 = sWhi[(8 * s + t + 4) * 136 + n0];
        const uint32_t bl0 = sWlo[(8 * s + t) * 136 + n0];
        const uint32_t bl1 = sWlo[(8 * s + t + 4) * 136 + n0];

        mma16816(c0, ah0, ah1, ah2, ah3, bh0, bh1);   // hi*hi
        mma16816(c0, ah0, ah1, ah2, ah3, bl0, bl1);   // hi*lo
        mma16816(c0, al0, al1, al2, al3, bh0, bh1);   // lo*hi
    }

    const int col = wid * 8 + 2 * t;
    const float bx = bias[col], by = bias[col + 1];
    const float x0 = fmaxf(c0[0] + bx, 0.f);
    const float x1 = fmaxf(c0[1] + by, 0.f);
    const float x2 = fmaxf(c0[2] + bx, 0.f);
    const float x3 = fmaxf(c0[3] + by, 0.f);
    if (F32OUT) {
        *(float2*)(sMout + g * 132 + col)       = make_float2(x0, x1);
        *(float2*)(sMout + (g + 8) * 132 + col) = make_float2(x2, x3);
    } else {
        uint32_t hp, lp;
        split2u(x0, x1, hp, lp);
        *(uint32_t*)(sOutHi + g * KPAD + col) = hp;
        *(uint32_t*)(sOutLo + g * KPAD + col) = lp;
        split2u(x2, x3, hp, lp);
        *(uint32_t*)(sOutHi + (g + 8) * KPAD + col) = hp;
        *(uint32_t*)(sOutLo + (g + 8) * KPAD + col) = lp;
    }
}

__global__ __launch_bounds__(NT, 1) void gcnn_tc_kernel(
    const float* __restrict__ obs,
    const float* __restrict__ W1,  const float* __restrict__ b1,
    const float* __restrict__ W2,  const float* __restrict__ b2,
    const float* __restrict__ Wm1, const float* __restrict__ bm1,
    const float* __restrict__ Wm2, const float* __restrict__ bm2,
    float* __restrict__ out, int std_off)
{
    extern __shared__ __align__(16) char smem[];
    uint32_t* sW2h = (uint32_t*)(smem + OW2H);
    uint32_t* sW2l = (uint32_t*)(smem + OW2L);
    uint32_t* sM1h = (uint32_t*)(smem + OM1H);
    uint32_t* sM1l = (uint32_t*)(smem + OM1L);
    unsigned short* sA1h = (unsigned short*)(smem + OA1H);
    unsigned short* sA1l = (unsigned short*)(smem + OA1L);
    unsigned short* sA2h = (unsigned short*)(smem + OA2H);
    unsigned short* sA2l = (unsigned short*)(smem + OA2L);
    float*  sM    = (float*)(smem + OSM);
    float*  sFB   = (float*)(smem + OFB);
    float2* sPart = (float2*)(smem + OPART);
    float*  sB2   = (float*)(smem + OB2V);
    float*  sBm1  = (float*)(smem + OBM1);
    float*  sWm2v = (float*)(smem + OWM2);
    float*  sBm2  = (float*)(smem + OBM2);
    float*  sP    = (float*)(smem + OSP);
    float*  sO    = (float*)(smem + OSO);

    const int tid = threadIdx.x, wid = tid >> 5, lane = tid & 31;
    const int base = blockIdx.x * MR;

    // ---- fbar partials first (their LDGs overlap the conversion LDGs) ----
    float fb0 = 0.f, fb1 = 0.f;
    if (tid < 448) {
        const int r = tid & 15, pq = tid >> 4;
        const int p = pq % 7, q = pq / 7;
        const float* s = obs + (size_t)(base + r) * 512 + 2 + 2 * p + q * 128;
        #pragma unroll
        for (int n = 0; n < 8; n++) {
            const float2 v = *(const float2*)(s + n * 16);
            fb0 += v.x; fb1 += v.y;
        }
    }

    // ---- in-kernel weight conversion: pair-packed, coalesced both sides ----
    convert_w_pp(W2,  sW2h, sW2l, tid);
    convert_w_pp(Wm1, sM1h, sM1l, tid);

    // ---- small params ----
    sWm2v[tid] = Wm2[tid];
    if (tid < 128) { sB2[tid] = b2[tid]; sBm1[tid] = bm1[tid]; }
    if (tid < 4) sBm2[tid] = bm2[tid];
    if (tid < 448) sPart[(tid & 15) * 28 + (tid >> 4)] = make_float2(fb0, fb1);
    __syncthreads();

    // ---- fbar reduce: 112 threads (r, p) ----
    if (tid < 112) {
        const int r = tid & 15, p = tid >> 4;
        float s0 = 0.f, s1 = 0.f;
        #pragma unroll
        for (int q = 0; q < 4; q++) {
            const float2 v = sPart[r * 28 + q * 7 + p];
            s0 += v.x; s1 += v.y;
        }
        sFB[r * 16 + 2 * p]     = s0 * 0.03125f;
        sFB[r * 16 + 2 * p + 1] = s1 * 0.03125f;
    }
    __syncthreads();

    // ---- L1 scalar f32: h1 = relu(fbar @ W1 + b1) -> A2 bf16 hi/lo ----
    {
        const int r = tid >> 5, j = tid & 31, c0 = 4 * j;
        float4 acc = *(const float4*)(b1 + c0);
        #pragma unroll
        for (int d = 0; d < 14; d++) {
            const float f = sFB[r * 16 + d];
            const float4 w = *(const float4*)(W1 + d * 128 + c0);
            acc.x = fmaf(f, w.x, acc.x);
            acc.y = fmaf(f, w.y, acc.y);
            acc.z = fmaf(f, w.z, acc.z);
            acc.w = fmaf(f, w.w, acc.w);
        }
        acc.x = fmaxf(acc.x, 0.f); acc.y = fmaxf(acc.y, 0.f);
        acc.z = fmaxf(acc.z, 0.f); acc.w = fmaxf(acc.w, 0.f);
        uint32_t hp, lp;
        split2u(acc.x, acc.y, hp, lp);
        ((uint32_t*)sA2h)[r * (KPAD / 2) + 2 * j]     = hp;
        ((uint32_t*)sA2l)[r * (KPAD / 2) + 2 * j]     = lp;
        split2u(acc.z, acc.w, hp, lp);
        ((uint32_t*)sA2h)[r * (KPAD / 2) + 2 * j + 1] = hp;
        ((uint32_t*)sA2l)[r * (KPAD / 2) + 2 * j + 1] = lp;
    }
    __syncthreads();

    // ---- L2: h2 = relu(h1 @ W2 + b2) : A2 -> A1 ----
    layer128<false>(sA2h, sA2l, sW2h, sW2l, sB2, sA1h, sA1l, nullptr, wid, lane);
    __syncthreads();

    // ---- L3: m = relu(h2 @ Wm1 + bm1) : A1 -> sM f32 ----
    layer128<true>(sA1h, sA1l, sM1h, sM1l, sBm1, nullptr, nullptr, sM, wid, lane);
    __syncthreads();

    // ---- tail: o = m @ Wm2 + bm2 : 512 = 16r x 4c x 8 k-slices ----
    {
        const int r = tid >> 5, cc = (tid >> 3) & 3, s = tid & 7;
        float p = 0.f;
        #pragma unroll
        for (int i = 0; i < 16; i++) {
            const int k = s * 16 + i;
            p = fmaf(sM[r * 132 + k], sWm2v[k * 4 + cc], p);
        }
        sP[tid] = p;
    }
    __syncthreads();
    if (tid < 64) {
        const int r = tid >> 2, cc = tid & 3;
        float o = sBm2[cc];
        #pragma unroll
        for (int s = 0; s < 8; s++) o += sP[r * 32 + cc * 8 + s];
        if (cc >= 2) o = __expf(-5.0f + 3.5f * (tanhf(o) + 1.0f));
        sO[r * 4 + cc] = o;    // [mu0, mu1, std0, std1]
    }
    __syncthreads();

    // ---- write: 512 float4 stores, one per thread, coalesced ----
    {
        const int plane = tid >> 8;
        const int r = (tid >> 4) & 15;
        const int q = tid & 15;
        const float v0 = sO[r * 4 + 2 * plane];
        const float v1 = sO[r * 4 + 2 * plane + 1];
        float* dst = out + (plane ? (size_t)std_off : 0) + (size_t)(base + r) * 64;
        ((float4*)dst)[q] = make_float4(v0, v1, v0, v1);
    }
}

extern "C" void kernel_launch(void* const* d_in, const int* in_sizes, int n_in,
                              void* d_out, int out_size) {
    const float* obs = (const float*)d_in[0];
    const float* W1  = (const float*)d_in[1];
    const float* b1  = (const float*)d_in[2];
    const float* W2  = (const float*)d_in[3];
    const float* b2  = (const float*)d_in[4];
    const float* Wm1 = (const float*)d_in[5];
    const float* bm1 = (const float*)d_in[6];
    const float* Wm2 = (const float*)d_in[7];
    const float* bm2 = (const float*)d_in[8];
    float* out = (float*)d_out;

    const int bs = in_sizes[0] / 512;     // 1024
    const int std_off = bs * 64;
    const int grid = bs / MR;             // 64

    cudaFuncSetAttribute(gcnn_tc_kernel,
                         cudaFuncAttributeMaxDynamicSharedMemorySize, SMEM_BYTES);
    gcnn_tc_kernel<<<grid, NT, SMEM_BYTES>>>(obs, W1, b1, W2, b2, Wm1, bm1,
                                             Wm2, bm2, out, std_off);
}